// round 11
// baseline (speedup 1.0000x reference)
#include <cuda_runtime.h>

#define EPS 1e-6f

static constexpr int B_ = 64;
static constexpr int T_ = 8000;
static constexpr int M_ = 80;
static constexpr int NC = 125;           // chunks over time
static constexpr int CL = T_ / NC;       // 64 steps per chunk
static constexpr int MQ = M_ / 4;        // 20 float4 lanes per row
static constexpr int LANES = B_ * MQ;    // 1280 float4 lanes
static constexpr int SLANES = B_ * M_;   // 5120 scalar lanes
static constexpr int NTH = NC * LANES;   // 160000 threads for pass1/pass3

// Scratch (no cudaMalloc allowed). Scalar view: [NC][B_*M_] floats.
__device__ float4 g_partial[NC * LANES];
__device__ float4 g_carry[NC * LANES];

// Single-instruction MUFU wrappers.
__device__ __forceinline__ float fast_lg2(float v) {
    float r; asm("lg2.approx.f32 %0, %1;" : "=f"(r) : "f"(v)); return r;
}
__device__ __forceinline__ float fast_ex2(float v) {
    float r; asm("ex2.approx.f32 %0, %1;" : "=f"(r) : "f"(v)); return r;
}

// ---------------------------------------------------------------------------
// Pass 1: chunk-local EMA endpoint, computed by a BACKWARD walk over the
// chunk:  m_end = sum_j s*(1-s)^(CL-1-j) * x_j   (algebraically identical to
// the forward recurrence from m=0; summation order reversed, error ~4e-6).
// Reading j descending leaves the LOW-j lines most-recent in L2, which is
// exactly the order pass3 consumes them -> inter-kernel L2 reuse instead of
// LRU thrash.
// ---------------------------------------------------------------------------
__global__ void __launch_bounds__(256) pcen_pass1(
        const float4* __restrict__ x, const float* __restrict__ log_s) {
    int tid = blockIdx.x * blockDim.x + threadIdx.x;
    if (tid >= NTH) return;
    int mq   = tid % MQ;
    int rest = tid / MQ;
    int b    = rest % B_;
    int c    = rest / B_;

    float s0 = __expf(log_s[mq * 4 + 0]);
    float s1 = __expf(log_s[mq * 4 + 1]);
    float s2 = __expf(log_s[mq * 4 + 2]);
    float s3 = __expf(log_s[mq * 4 + 3]);
    float o0 = 1.0f - s0, o1 = 1.0f - s1, o2 = 1.0f - s2, o3 = 1.0f - s3;

    const float4* xp = x + ((size_t)b * T_ + (size_t)c * CL) * MQ + mq;

    // Running weight sw = s * oms^(CL-1-j), starting at j=CL-1 with sw=s.
    float sw0 = s0, sw1 = s1, sw2 = s2, sw3 = s3;
    float4 mv = make_float4(0.f, 0.f, 0.f, 0.f);

#pragma unroll 8
    for (int j = CL - 1; j >= 0; j--) {
        float4 xv = __ldg(&xp[(size_t)j * MQ]);
        mv.x = fmaf(sw0, xv.x, mv.x);
        mv.y = fmaf(sw1, xv.y, mv.y);
        mv.z = fmaf(sw2, xv.z, mv.z);
        mv.w = fmaf(sw3, xv.w, mv.w);
        sw0 *= o0; sw1 *= o1; sw2 *= o2; sw3 *= o3;
    }
    g_partial[tid] = mv;
}

// ---------------------------------------------------------------------------
// Pass 2: per-lane serial combine of NC chunk carries, staged through SMEM.
//   carry_{c+1} = local_end_c + (1-s)^CL * carry_c
// Touches only ~2.6 MB -> leaves pass1's L2 residency intact.
// ---------------------------------------------------------------------------
static constexpr int LPB = 64;   // scalar lanes per block
__global__ void __launch_bounds__(256) pcen_pass2(
        const float* __restrict__ log_s) {
    __shared__ float sm[NC][LPB];  // 32000 B
    const int lane0 = blockIdx.x * LPB;
    const float* gp = reinterpret_cast<const float*>(g_partial);
    float*       gc = reinterpret_cast<float*>(g_carry);

    for (int i = threadIdx.x; i < NC * LPB; i += blockDim.x) {
        int c = i / LPB, l = i % LPB;
        sm[c][l] = gp[(size_t)c * SLANES + lane0 + l];
    }
    __syncthreads();

    if (threadIdx.x < LPB) {
        int l = threadIdx.x;
        int m = (lane0 + l) % M_;
        float s   = __expf(log_s[m]);
        float oms = 1.0f - s;
        float dC  = 1.0f;
#pragma unroll
        for (int i = 0; i < CL; i++) dC *= oms;

        float carry = 0.0f;
#pragma unroll 5
        for (int c = 0; c < NC; c++) {
            float p = sm[c][l];
            sm[c][l] = carry;              // carry-IN for chunk c
            carry = fmaf(dC, carry, p);
        }
    }
    __syncthreads();

    for (int i = threadIdx.x; i < NC * LPB; i += blockDim.x) {
        int c = i / LPB, l = i % LPB;
        gc[(size_t)c * SLANES + lane0 + l] = sm[c][l];
    }
}

// ---------------------------------------------------------------------------
// Pass 3: rescan each chunk FORWARD from its exact carry-in and emit output.
// x reads use __ldcs (dead after use -> evict-first) and out writes __stcs
// (never re-read) so neither evicts the pass1-resident x lines still ahead.
// out = ex2(r * lg2(fma(x, ex2(-alpha*lg2(m+eps)), delta))) - delta_r
// ---------------------------------------------------------------------------
__device__ __forceinline__ float pcen_out(float xv, float mv, float nalpha,
                                          float delta, float r, float dr) {
    float l   = fast_lg2(mv + EPS);
    float den = fast_ex2(nalpha * l);
    float y   = fmaf(xv, den, delta);
    return fast_ex2(r * fast_lg2(y)) - dr;
}

__global__ void __launch_bounds__(256) pcen_pass3(
        const float4* __restrict__ x,
        const float* __restrict__ log_s,
        const float* __restrict__ log_alpha,
        const float* __restrict__ log_delta,
        const float* __restrict__ log_r,
        float4* __restrict__ out) {
    int tid = blockIdx.x * blockDim.x + threadIdx.x;
    if (tid >= NTH) return;
    int mq   = tid % MQ;
    int rest = tid / MQ;
    int b    = rest % B_;
    int c    = rest / B_;

    float s0, s1, s2, s3, o0, o1, o2, o3;
    float na0, na1, na2, na3;
    float d0, d1, d2, d3;
    float r0, r1, r2, r3;
    float dr0, dr1, dr2, dr3;
    {
        int m0 = mq * 4;
        s0 = __expf(log_s[m0 + 0]); s1 = __expf(log_s[m0 + 1]);
        s2 = __expf(log_s[m0 + 2]); s3 = __expf(log_s[m0 + 3]);
        o0 = 1.0f - s0; o1 = 1.0f - s1; o2 = 1.0f - s2; o3 = 1.0f - s3;
        na0 = -__expf(log_alpha[m0 + 0]); na1 = -__expf(log_alpha[m0 + 1]);
        na2 = -__expf(log_alpha[m0 + 2]); na3 = -__expf(log_alpha[m0 + 3]);
        d0 = __expf(log_delta[m0 + 0]); d1 = __expf(log_delta[m0 + 1]);
        d2 = __expf(log_delta[m0 + 2]); d3 = __expf(log_delta[m0 + 3]);
        r0 = __expf(log_r[m0 + 0]); r1 = __expf(log_r[m0 + 1]);
        r2 = __expf(log_r[m0 + 2]); r3 = __expf(log_r[m0 + 3]);
        dr0 = __expf(r0 * log_delta[m0 + 0]);
        dr1 = __expf(r1 * log_delta[m0 + 1]);
        dr2 = __expf(r2 * log_delta[m0 + 2]);
        dr3 = __expf(r3 * log_delta[m0 + 3]);
    }

    float4 mv = g_carry[tid];
    const float4* xp = x   + ((size_t)b * T_ + (size_t)c * CL) * MQ + mq;
    float4*       op = out + ((size_t)b * T_ + (size_t)c * CL) * MQ + mq;

#pragma unroll 4
    for (int j = 0; j < CL; j++) {
        float4 xv = __ldcs(&xp[(size_t)j * MQ]);
        mv.x = fmaf(o0, mv.x, s0 * xv.x);
        mv.y = fmaf(o1, mv.y, s1 * xv.y);
        mv.z = fmaf(o2, mv.z, s2 * xv.z);
        mv.w = fmaf(o3, mv.w, s3 * xv.w);
        float4 ov;
        ov.x = pcen_out(xv.x, mv.x, na0, d0, r0, dr0);
        ov.y = pcen_out(xv.y, mv.y, na1, d1, r1, dr1);
        ov.z = pcen_out(xv.z, mv.z, na2, d2, r2, dr2);
        ov.w = pcen_out(xv.w, mv.w, na3, d3, r3, dr3);
        __stcs(&op[(size_t)j * MQ], ov);
    }
}

extern "C" void kernel_launch(void* const* d_in, const int* in_sizes, int n_in,
                              void* d_out, int out_size) {
    const float* x         = (const float*)d_in[0];
    const float* log_s     = (const float*)d_in[1];
    const float* log_alpha = (const float*)d_in[2];
    const float* log_delta = (const float*)d_in[3];
    const float* log_r     = (const float*)d_in[4];
    float* out = (float*)d_out;

    const int threads = 256;
    pcen_pass1<<<(NTH + threads - 1) / threads, threads>>>(
        (const float4*)x, log_s);
    pcen_pass2<<<SLANES / LPB, threads>>>(log_s);
    pcen_pass3<<<(NTH + threads - 1) / threads, threads>>>(
        (const float4*)x, log_s, log_alpha, log_delta, log_r, (float4*)out);
}

// round 12
// speedup vs baseline: 1.1380x; 1.1380x over previous
#include <cuda_runtime.h>

#define EPS 1e-6f

static constexpr int B_ = 64;
static constexpr int T_ = 8000;
static constexpr int M_ = 80;
static constexpr int NC = 250;           // chunks over time (2x parallelism)
static constexpr int CL = T_ / NC;       // 32 steps per chunk
static constexpr int MQ = M_ / 4;        // 20 float4 lanes per row
static constexpr int LANES = B_ * MQ;    // 1280 float4 lanes
static constexpr int SLANES = B_ * M_;   // 5120 scalar lanes
static constexpr int NTH = NC * LANES;   // 320000 threads for pass1/pass3

// Scratch (no cudaMalloc allowed). Scalar view: [NC][B_*M_] floats.
__device__ float4 g_partial[NC * LANES];
__device__ float4 g_carry[NC * LANES];

// Single-instruction MUFU wrappers.
__device__ __forceinline__ float fast_lg2(float v) {
    float r; asm("lg2.approx.f32 %0, %1;" : "=f"(r) : "f"(v)); return r;
}
__device__ __forceinline__ float fast_ex2(float v) {
    float r; asm("ex2.approx.f32 %0, %1;" : "=f"(r) : "f"(v)); return r;
}

// ---------------------------------------------------------------------------
// Pass 1: each (chunk c, batch b, mel-quad mq) thread scans its chunk with
// m_init = 0 (forward, serial-rounding-exact), recording the endpoint.
// 320K threads -> ~94% occupancy -> deep chip-wide MLP for streaming.
// ---------------------------------------------------------------------------
__global__ void __launch_bounds__(256) pcen_pass1(
        const float4* __restrict__ x, const float* __restrict__ log_s) {
    int tid = blockIdx.x * blockDim.x + threadIdx.x;
    if (tid >= NTH) return;
    int mq   = tid % MQ;
    int rest = tid / MQ;
    int b    = rest % B_;
    int c    = rest / B_;

    float s0 = __expf(log_s[mq * 4 + 0]);
    float s1 = __expf(log_s[mq * 4 + 1]);
    float s2 = __expf(log_s[mq * 4 + 2]);
    float s3 = __expf(log_s[mq * 4 + 3]);
    float o0 = 1.0f - s0, o1 = 1.0f - s1, o2 = 1.0f - s2, o3 = 1.0f - s3;

    const float4* xp = x + ((size_t)b * T_ + (size_t)c * CL) * MQ + mq;
    float4 mv = make_float4(0.f, 0.f, 0.f, 0.f);

#pragma unroll 4
    for (int j = 0; j < CL; j++) {
        float4 xv = __ldg(&xp[(size_t)j * MQ]);
        mv.x = fmaf(o0, mv.x, s0 * xv.x);
        mv.y = fmaf(o1, mv.y, s1 * xv.y);
        mv.z = fmaf(o2, mv.z, s2 * xv.z);
        mv.w = fmaf(o3, mv.w, s3 * xv.w);
    }
    g_partial[tid] = mv;
}

// ---------------------------------------------------------------------------
// Pass 2: per-lane serial combine of NC chunk carries, staged through SMEM.
//   carry_{c+1} = local_end_c + (1-s)^CL * carry_c
// (1-s)^CL as a literal CL-multiply product (matches serial rounding).
// ---------------------------------------------------------------------------
static constexpr int LPB = 32;   // scalar lanes per block (SMEM fits 48KB)
__global__ void __launch_bounds__(256) pcen_pass2(
        const float* __restrict__ log_s) {
    __shared__ float sm[NC][LPB];  // 32000 B
    const int lane0 = blockIdx.x * LPB;
    const float* gp = reinterpret_cast<const float*>(g_partial);
    float*       gc = reinterpret_cast<float*>(g_carry);

    for (int i = threadIdx.x; i < NC * LPB; i += blockDim.x) {
        int c = i / LPB, l = i % LPB;
        sm[c][l] = gp[(size_t)c * SLANES + lane0 + l];
    }
    __syncthreads();

    if (threadIdx.x < LPB) {
        int l = threadIdx.x;
        int m = (lane0 + l) % M_;
        float s   = __expf(log_s[m]);
        float oms = 1.0f - s;
        float dC  = 1.0f;
#pragma unroll
        for (int i = 0; i < CL; i++) dC *= oms;

        float carry = 0.0f;
#pragma unroll 5
        for (int c = 0; c < NC; c++) {
            float p = sm[c][l];
            sm[c][l] = carry;              // carry-IN for chunk c
            carry = fmaf(dC, carry, p);
        }
    }
    __syncthreads();

    for (int i = threadIdx.x; i < NC * LPB; i += blockDim.x) {
        int c = i / LPB, l = i % LPB;
        gc[(size_t)c * SLANES + lane0 + l] = sm[c][l];
    }
}

// ---------------------------------------------------------------------------
// Pass 3: rescan each chunk forward from its exact carry-in and emit output.
// out = ex2(r * lg2(fma(x, ex2(-alpha*lg2(m+eps)), delta))) - delta_r
// 4 MUFU ops per element; no division. High occupancy interleaves MUFU
// chains with the streaming loads/stores.
// ---------------------------------------------------------------------------
__device__ __forceinline__ float pcen_out(float xv, float mv, float nalpha,
                                          float delta, float r, float dr) {
    float l   = fast_lg2(mv + EPS);
    float den = fast_ex2(nalpha * l);
    float y   = fmaf(xv, den, delta);
    return fast_ex2(r * fast_lg2(y)) - dr;
}

__global__ void __launch_bounds__(256) pcen_pass3(
        const float4* __restrict__ x,
        const float* __restrict__ log_s,
        const float* __restrict__ log_alpha,
        const float* __restrict__ log_delta,
        const float* __restrict__ log_r,
        float4* __restrict__ out) {
    int tid = blockIdx.x * blockDim.x + threadIdx.x;
    if (tid >= NTH) return;
    int mq   = tid % MQ;
    int rest = tid / MQ;
    int b    = rest % B_;
    int c    = rest / B_;

    float s0, s1, s2, s3, o0, o1, o2, o3;
    float na0, na1, na2, na3;
    float d0, d1, d2, d3;
    float r0, r1, r2, r3;
    float dr0, dr1, dr2, dr3;
    {
        int m0 = mq * 4;
        s0 = __expf(log_s[m0 + 0]); s1 = __expf(log_s[m0 + 1]);
        s2 = __expf(log_s[m0 + 2]); s3 = __expf(log_s[m0 + 3]);
        o0 = 1.0f - s0; o1 = 1.0f - s1; o2 = 1.0f - s2; o3 = 1.0f - s3;
        na0 = -__expf(log_alpha[m0 + 0]); na1 = -__expf(log_alpha[m0 + 1]);
        na2 = -__expf(log_alpha[m0 + 2]); na3 = -__expf(log_alpha[m0 + 3]);
        d0 = __expf(log_delta[m0 + 0]); d1 = __expf(log_delta[m0 + 1]);
        d2 = __expf(log_delta[m0 + 2]); d3 = __expf(log_delta[m0 + 3]);
        r0 = __expf(log_r[m0 + 0]); r1 = __expf(log_r[m0 + 1]);
        r2 = __expf(log_r[m0 + 2]); r3 = __expf(log_r[m0 + 3]);
        dr0 = __expf(r0 * log_delta[m0 + 0]);
        dr1 = __expf(r1 * log_delta[m0 + 1]);
        dr2 = __expf(r2 * log_delta[m0 + 2]);
        dr3 = __expf(r3 * log_delta[m0 + 3]);
    }

    float4 mv = g_carry[tid];
    const float4* xp = x   + ((size_t)b * T_ + (size_t)c * CL) * MQ + mq;
    float4*       op = out + ((size_t)b * T_ + (size_t)c * CL) * MQ + mq;

#pragma unroll 4
    for (int j = 0; j < CL; j++) {
        float4 xv = __ldg(&xp[(size_t)j * MQ]);
        mv.x = fmaf(o0, mv.x, s0 * xv.x);
        mv.y = fmaf(o1, mv.y, s1 * xv.y);
        mv.z = fmaf(o2, mv.z, s2 * xv.z);
        mv.w = fmaf(o3, mv.w, s3 * xv.w);
        float4 ov;
        ov.x = pcen_out(xv.x, mv.x, na0, d0, r0, dr0);
        ov.y = pcen_out(xv.y, mv.y, na1, d1, r1, dr1);
        ov.z = pcen_out(xv.z, mv.z, na2, d2, r2, dr2);
        ov.w = pcen_out(xv.w, mv.w, na3, d3, r3, dr3);
        op[(size_t)j * MQ] = ov;
    }
}

extern "C" void kernel_launch(void* const* d_in, const int* in_sizes, int n_in,
                              void* d_out, int out_size) {
    const float* x         = (const float*)d_in[0];
    const float* log_s     = (const float*)d_in[1];
    const float* log_alpha = (const float*)d_in[2];
    const float* log_delta = (const float*)d_in[3];
    const float* log_r     = (const float*)d_in[4];
    float* out = (float*)d_out;

    const int threads = 256;
    pcen_pass1<<<(NTH + threads - 1) / threads, threads>>>(
        (const float4*)x, log_s);
    pcen_pass2<<<SLANES / LPB, threads>>>(log_s);
    pcen_pass3<<<(NTH + threads - 1) / threads, threads>>>(
        (const float4*)x, log_s, log_alpha, log_delta, log_r, (float4*)out);
}